// round 2
// baseline (speedup 1.0000x reference)
#include <cuda_runtime.h>
#include <cstdint>

// Output: [1024, 201000] float32 = one_hot(h,1e5) ++ one_hot(r,1e3) ++ one_hot(t,1e5).
// Single fused kernel: every thread writes one float4; values computed directly
// (no zero-then-scatter second pass).

static constexpr int BATCH = 1024;
static constexpr int ENTITIES_N = 100000;
static constexpr int RELATIONS_N = 1000;
static constexpr int WIDTH = ENTITIES_N * 2 + RELATIONS_N;  // 201000
static constexpr int WIDTH4 = WIDTH / 4;                    // 50250

__global__ void onehot_fill_kernel(float4* __restrict__ out,
                                   const int* __restrict__ hID,
                                   const int* __restrict__ rID,
                                   const int* __restrict__ tID) {
    const int col4 = blockIdx.x * blockDim.x + threadIdx.x;
    if (col4 >= WIDTH4) return;
    const int row = blockIdx.y;

    // Row-broadcast loads — L1/L2 hits for all but the first warp touching them.
    const int c0 = hID[row];
    const int c1 = ENTITIES_N + rID[row];
    const int c2 = ENTITIES_N + RELATIONS_N + tID[row];

    const int base = col4 * 4;
    float4 v;
    v.x = (base + 0 == c0 || base + 0 == c1 || base + 0 == c2) ? 1.0f : 0.0f;
    v.y = (base + 1 == c0 || base + 1 == c1 || base + 1 == c2) ? 1.0f : 0.0f;
    v.z = (base + 2 == c0 || base + 2 == c1 || base + 2 == c2) ? 1.0f : 0.0f;
    v.w = (base + 3 == c0 || base + 3 == c1 || base + 3 == c2) ? 1.0f : 0.0f;

    out[(long long)row * WIDTH4 + col4] = v;
}

extern "C" void kernel_launch(void* const* d_in, const int* in_sizes, int n_in,
                              void* d_out, int out_size) {
    // inputs: z (float32, unused), hID (int32), rID (int32), tID (int32)
    const int* hID = (const int*)d_in[1];
    const int* rID = (const int*)d_in[2];
    const int* tID = (const int*)d_in[3];

    const int threads = 256;
    dim3 grid((WIDTH4 + threads - 1) / threads, BATCH, 1);
    onehot_fill_kernel<<<grid, threads>>>((float4*)d_out, hID, rID, tID);
}

// round 3
// speedup vs baseline: 1.2147x; 1.2147x over previous
#include <cuda_runtime.h>
#include <cstdint>

// Output: [1024, 201000] fp32 = one_hot(h,1e5) ++ one_hot(r,1e3) ++ one_hot(t,1e5).
// Single kernel. Block-uniform hot-column check: 94% of blocks take a pure
// STG.128 fill path (no per-element compares); only blocks containing a hot
// column run the compare path.

static constexpr int BATCH = 1024;
static constexpr int ENTITIES_N = 100000;
static constexpr int RELATIONS_N = 1000;
static constexpr int WIDTH = ENTITIES_N * 2 + RELATIONS_N;  // 201000 floats
static constexpr int WIDTH4 = WIDTH / 4;                    // 50250 float4s
static constexpr int THREADS = 256;
static constexpr int F4_PER_THREAD = 4;
static constexpr int F4_PER_BLOCK = THREADS * F4_PER_THREAD;          // 1024
static constexpr int BLOCKS_PER_ROW = (WIDTH4 + F4_PER_BLOCK - 1) / F4_PER_BLOCK;  // 50

__global__ void __launch_bounds__(THREADS) onehot_kernel(
    float4* __restrict__ out,
    const int* __restrict__ hID,
    const int* __restrict__ rID,
    const int* __restrict__ tID) {

    const int row = blockIdx.y;
    const int blk = blockIdx.x;
    const int tid = threadIdx.x;
    const int base4 = blk * F4_PER_BLOCK;   // first float4 index of this block (within row)

    // Hot columns for this row (float indices). Broadcast loads -> L1 hits.
    const int c0 = __ldg(hID + row);
    const int c1 = ENTITIES_N + __ldg(rID + row);
    const int c2 = ENTITIES_N + RELATIONS_N + __ldg(tID + row);

    const int lo = base4 * 4;               // float index range covered by block
    const int hi = lo + F4_PER_BLOCK * 4;

    float4* p = out + (long long)row * WIDTH4 + base4 + tid;
    const float4 z = make_float4(0.f, 0.f, 0.f, 0.f);

    // Block-uniform condition (lo/hi block-uniform, c* row-uniform).
    const bool hot = (c0 >= lo && c0 < hi) || (c1 >= lo && c1 < hi) || (c2 >= lo && c2 < hi);
    const bool full = (base4 + F4_PER_BLOCK <= WIDTH4);   // uniform: all but last block/row

    if (!hot) {
        if (full) {
            // Fast path: 4 coalesced STG.128, zero per-element ALU.
            p[0 * THREADS] = z;
            p[1 * THREADS] = z;
            p[2 * THREADS] = z;
            p[3 * THREADS] = z;
        } else {
            #pragma unroll
            for (int k = 0; k < F4_PER_THREAD; k++) {
                if (base4 + k * THREADS + tid < WIDTH4) p[k * THREADS] = z;
            }
        }
    } else {
        // Rare path (~6% of blocks): per-element compares.
        #pragma unroll
        for (int k = 0; k < F4_PER_THREAD; k++) {
            const int i4 = base4 + k * THREADS + tid;
            if (i4 < WIDTH4) {
                const int b = i4 * 4;
                float4 v;
                v.x = (b + 0 == c0 || b + 0 == c1 || b + 0 == c2) ? 1.f : 0.f;
                v.y = (b + 1 == c0 || b + 1 == c1 || b + 1 == c2) ? 1.f : 0.f;
                v.z = (b + 2 == c0 || b + 2 == c1 || b + 2 == c2) ? 1.f : 0.f;
                v.w = (b + 3 == c0 || b + 3 == c1 || b + 3 == c2) ? 1.f : 0.f;
                p[k * THREADS] = v;
            }
        }
    }
}

extern "C" void kernel_launch(void* const* d_in, const int* in_sizes, int n_in,
                              void* d_out, int out_size) {
    // inputs: z (float32, unused), hID (int32), rID (int32), tID (int32)
    const int* hID = (const int*)d_in[1];
    const int* rID = (const int*)d_in[2];
    const int* tID = (const int*)d_in[3];

    dim3 grid(BLOCKS_PER_ROW, BATCH, 1);
    onehot_kernel<<<grid, THREADS>>>((float4*)d_out, hID, rID, tID);
}